// round 1
// baseline (speedup 1.0000x reference)
#include <cuda_runtime.h>
#include <cstdint>

// Problem dims (fixed for this dataset entry)
#define MTOK 8192   // B*S = 4*2048
#define DDIM 2048   // D
#define FDIM 8192   // F
#define RRANK 16    // LoRA rank

// GEMM tiling
#define BM 128
#define BN 128
#define BK 16
#define TM 8
#define TN 8

// ---------------- scratch (allocation-free: __device__ globals) ----------------
__device__ float g_scratch[(size_t)MTOK * FDIM];   // 256 MB: y1 then x3 (in place)
__device__ float g_t_gate[MTOK * RRANK];
__device__ float g_t_up[MTOK * RRANK];
__device__ float g_t_down[MTOK * RRANK];

// ---------------- LoRA-A projection: T[m,r] = sum_k X[m,k]*A[k,r] ----------------
// One warp per row; optional second (A1,T1) pair computed in the same pass over X.
__global__ __launch_bounds__(256)
void lora_a_kernel(const float* __restrict__ X, int K,
                   const float* __restrict__ A0, float* __restrict__ T0,
                   const float* __restrict__ A1, float* __restrict__ T1)
{
    int m    = blockIdx.x * 8 + (threadIdx.x >> 5);
    int lane = threadIdx.x & 31;

    float acc0[RRANK];
    float acc1[RRANK];
#pragma unroll
    for (int r = 0; r < RRANK; r++) { acc0[r] = 0.f; acc1[r] = 0.f; }

    const float* xr = X + (size_t)m * K;
    const bool dual = (A1 != nullptr);

    for (int k = lane; k < K; k += 32) {
        float x = __ldg(xr + k);
        const float4* a0 = reinterpret_cast<const float4*>(A0 + (size_t)k * RRANK);
#pragma unroll
        for (int q = 0; q < 4; q++) {
            float4 v = __ldg(a0 + q);
            acc0[q*4+0] += x * v.x;
            acc0[q*4+1] += x * v.y;
            acc0[q*4+2] += x * v.z;
            acc0[q*4+3] += x * v.w;
        }
        if (dual) {
            const float4* a1 = reinterpret_cast<const float4*>(A1 + (size_t)k * RRANK);
#pragma unroll
            for (int q = 0; q < 4; q++) {
                float4 v = __ldg(a1 + q);
                acc1[q*4+0] += x * v.x;
                acc1[q*4+1] += x * v.y;
                acc1[q*4+2] += x * v.z;
                acc1[q*4+3] += x * v.w;
            }
        }
    }

    // warp butterfly reduce
#pragma unroll
    for (int r = 0; r < RRANK; r++) {
#pragma unroll
        for (int off = 16; off > 0; off >>= 1) {
            acc0[r] += __shfl_xor_sync(0xffffffffu, acc0[r], off);
            acc1[r] += __shfl_xor_sync(0xffffffffu, acc1[r], off);
        }
    }
    if (lane == 0) {
#pragma unroll
        for (int r = 0; r < RRANK; r++) {
            T0[(size_t)m * RRANK + r] = acc0[r];
            if (dual) T1[(size_t)m * RRANK + r] = acc1[r];
        }
    }
}

// ---------------- tile FMA helper ----------------
__device__ __forceinline__
void mma_tile(float (&acc)[TM][TN],
              const float (&As)[BK][BM], const float (&Bs)[BK][BN],
              int ty, int tx)
{
#pragma unroll
    for (int kk = 0; kk < BK; kk++) {
        float4 a0 = *reinterpret_cast<const float4*>(&As[kk][ty * TM]);
        float4 a1 = *reinterpret_cast<const float4*>(&As[kk][ty * TM + 4]);
        float4 b0 = *reinterpret_cast<const float4*>(&Bs[kk][tx * TN]);
        float4 b1 = *reinterpret_cast<const float4*>(&Bs[kk][tx * TN + 4]);
        float ar[TM] = {a0.x, a0.y, a0.z, a0.w, a1.x, a1.y, a1.z, a1.w};
        float br[TN] = {b0.x, b0.y, b0.z, b0.w, b1.x, b1.y, b1.z, b1.w};
#pragma unroll
        for (int i = 0; i < TM; i++)
#pragma unroll
            for (int j = 0; j < TN; j++)
                acc[i][j] += ar[i] * br[j];
    }
}

// ---------------- GEMM with bias + LoRA-B epilogue tile + optional relu-gate ----------------
// C[m,n] = A[m,:]@B[:,n] + bias[n] + T[m,:]@Lb[:,n]        (Gate == nullptr)
// C[m,n] = relu(Gate[m,n]) * (A@B + bias + T@Lb)           (Gate != nullptr; C may alias Gate)
__global__ __launch_bounds__(256, 2)
void gemm_epi(const float* __restrict__ A, int lda,
              const float* __restrict__ B, int ldb,
              const float* __restrict__ bias,
              const float* __restrict__ T,    // [M, 16]
              const float* __restrict__ Lb,   // [16, N]
              float* __restrict__ C,
              const float* __restrict__ Gate,
              int M, int N, int K)
{
    __shared__ float As[BK][BM];
    __shared__ float Bs[BK][BN];

    const int tid = threadIdx.x;
    const int bm  = blockIdx.y * BM;
    const int bn  = blockIdx.x * BN;

    // loader indices
    const int arow = tid >> 2;          // 0..63   (A tile rows, +64 for second)
    const int acol = (tid & 3) * 4;     // 0,4,8,12
    const int brow = tid >> 5;          // 0..7    (B tile rows, +8 for second)
    const int bcol = (tid & 31) * 4;    // 0..124

    const int ty = tid >> 4;            // 0..15
    const int tx = tid & 15;            // 0..15

    float acc[TM][TN];
#pragma unroll
    for (int i = 0; i < TM; i++)
#pragma unroll
        for (int j = 0; j < TN; j++)
            acc[i][j] = 0.f;

    for (int k0 = 0; k0 < K; k0 += BK) {
#pragma unroll
        for (int h = 0; h < 2; h++) {
            int r = arow + 64 * h;
            float4 v = *reinterpret_cast<const float4*>(
                A + (size_t)(bm + r) * lda + k0 + acol);
            As[acol + 0][r] = v.x;
            As[acol + 1][r] = v.y;
            As[acol + 2][r] = v.z;
            As[acol + 3][r] = v.w;
        }
#pragma unroll
        for (int h = 0; h < 2; h++) {
            int r = brow + 8 * h;
            *reinterpret_cast<float4*>(&Bs[r][bcol]) =
                *reinterpret_cast<const float4*>(B + (size_t)(k0 + r) * ldb + bn + bcol);
        }
        __syncthreads();
        mma_tile(acc, As, Bs, ty, tx);
        __syncthreads();
    }

    // ---- LoRA contribution as one extra BK=16 tile: As <- T^T slice, Bs <- Lb slice ----
#pragma unroll
    for (int h = 0; h < 2; h++) {
        int r = arow + 64 * h;
        float4 v = *reinterpret_cast<const float4*>(T + (size_t)(bm + r) * RRANK + acol);
        As[acol + 0][r] = v.x;
        As[acol + 1][r] = v.y;
        As[acol + 2][r] = v.z;
        As[acol + 3][r] = v.w;
    }
#pragma unroll
    for (int h = 0; h < 2; h++) {
        int r = brow + 8 * h;
        *reinterpret_cast<float4*>(&Bs[r][bcol]) =
            *reinterpret_cast<const float4*>(Lb + (size_t)r * N + bn + bcol);
    }
    __syncthreads();
    mma_tile(acc, As, Bs, ty, tx);

    // ---- epilogue: bias (+ optional relu-gate), vectorized stores ----
#pragma unroll
    for (int i = 0; i < TM; i++) {
        int m = bm + ty * TM + i;
#pragma unroll
        for (int j = 0; j < TN; j += 4) {
            int n = bn + tx * TN + j;
            float4 o;
            o.x = acc[i][j + 0] + bias[n + 0];
            o.y = acc[i][j + 1] + bias[n + 1];
            o.z = acc[i][j + 2] + bias[n + 2];
            o.w = acc[i][j + 3] + bias[n + 3];
            if (Gate != nullptr) {
                float4 g = *reinterpret_cast<const float4*>(Gate + (size_t)m * N + n);
                o.x = fmaxf(g.x, 0.f) * o.x;
                o.y = fmaxf(g.y, 0.f) * o.y;
                o.z = fmaxf(g.z, 0.f) * o.z;
                o.w = fmaxf(g.w, 0.f) * o.w;
            }
            *reinterpret_cast<float4*>(C + (size_t)m * N + n) = o;
        }
    }
}

// ---------------- launcher ----------------
extern "C" void kernel_launch(void* const* d_in, const int* in_sizes, int n_in,
                              void* d_out, int out_size)
{
    const float* x1     = (const float*)d_in[0];
    const float* w_gate = (const float*)d_in[1];
    const float* b_gate = (const float*)d_in[2];
    const float* wga    = (const float*)d_in[3];   // w_gate_lora_a [D,16]
    const float* wgb    = (const float*)d_in[4];   // w_gate_lora_b [16,F]
    const float* w_up   = (const float*)d_in[5];
    const float* b_up   = (const float*)d_in[6];
    const float* wua    = (const float*)d_in[7];
    const float* wub    = (const float*)d_in[8];
    const float* w_down = (const float*)d_in[9];   // [F,D]
    const float* b_down = (const float*)d_in[10];
    const float* wda    = (const float*)d_in[11];  // [F,16]
    const float* wdb    = (const float*)d_in[12];  // [16,D]
    float* out = (float*)d_out;

    float *scratch, *tg, *tu, *td;
    cudaGetSymbolAddress((void**)&scratch, g_scratch);
    cudaGetSymbolAddress((void**)&tg, g_t_gate);
    cudaGetSymbolAddress((void**)&tu, g_t_up);
    cudaGetSymbolAddress((void**)&td, g_t_down);

    // 1) t_gate, t_up = x1 @ lora_a  (single pass over x1)
    lora_a_kernel<<<MTOK / 8, 256>>>(x1, DDIM, wga, tg, wua, tu);

    // 2) y1 = x1@w_gate + b_gate + t_gate@wgb  -> scratch
    gemm_epi<<<dim3(FDIM / BN, MTOK / BM), 256>>>(
        x1, DDIM, w_gate, FDIM, b_gate, tg, wgb, scratch, nullptr,
        MTOK, FDIM, DDIM);

    // 3) x3 = relu(y1) * (x1@w_up + b_up + t_up@wub)  -> scratch (in place)
    gemm_epi<<<dim3(FDIM / BN, MTOK / BM), 256>>>(
        x1, DDIM, w_up, FDIM, b_up, tu, wub, scratch, scratch,
        MTOK, FDIM, DDIM);

    // 4) t_down = x3 @ w_down_lora_a
    lora_a_kernel<<<MTOK / 8, 256>>>(scratch, FDIM, wda, td, nullptr, nullptr);

    // 5) out = x3@w_down + b_down + t_down@wdb
    gemm_epi<<<dim3(DDIM / BN, MTOK / BM), 256>>>(
        scratch, FDIM, w_down, DDIM, b_down, td, wdb, out, nullptr,
        MTOK, DDIM, FDIM);
}